// round 2
// baseline (speedup 1.0000x reference)
#include <cuda_runtime.h>

#define T_STEPS 8192
#define IDIM 256
#define HDIM 1024
#define NBLOCKS 128
#define NTHREADS 256       // 8 warps; warp w handles h index j = 8*block + w
#define NAN_BITS 0x7fc00000u

// h history: row t holds h_{t-1} (input to step t). Row 0 = zeros (h_0).
// Rows 1..T start as sentinel NaN; a non-sentinel value == "published".
__device__ __align__(16) float g_hs[(T_STEPS + 1) * HDIM];

// Fill row 0 with zeros, rows 1..T with sentinel. One block per row.
__global__ void init_kernel() {
    unsigned int v = (blockIdx.x == 0) ? 0u : NAN_BITS;
    uint4 q = make_uint4(v, v, v, v);
    reinterpret_cast<uint4*>(g_hs + (size_t)blockIdx.x * HDIM)[threadIdx.x] = q;
}

__device__ __forceinline__ float sigmoid_fast(float x) {
    return 1.0f / (1.0f + __expf(-x));
}
__device__ __forceinline__ float tanh_fast(float x) {
    // tanh(x) = 2*sigmoid(2x) - 1, built on ex2.approx (rel err ~2^-22)
    return fmaf(2.0f, 1.0f / (1.0f + __expf(-2.0f * x)), -1.0f);
}

// Packed dual-FMA: d.xy += a.xy * b.xy  (Blackwell f32x2, PTX-only)
__device__ __forceinline__ void fma2(unsigned long long& d,
                                     unsigned long long a,
                                     unsigned long long b) {
    asm("fma.rn.f32x2 %0, %1, %2, %0;" : "+l"(d) : "l"(a), "l"(b));
}
__device__ __forceinline__ unsigned long long ld64(const float* p) {
    return *reinterpret_cast<const unsigned long long*>(p);
}
__device__ __forceinline__ float pairsum(unsigned long long v) {
    float2 f = *reinterpret_cast<float2*>(&v);
    return f.x + f.y;
}

__global__ void __launch_bounds__(NTHREADS, 1)
lstm_kernel(const float* __restrict__ seq,
            const float* __restrict__ W_ih,
            const float* __restrict__ W_hh,
            const float* __restrict__ b_ih,
            const float* __restrict__ b_hh)
{
    __shared__ __align__(16) float h_s[HDIM];

    const int tid  = threadIdx.x;
    const int warp = tid >> 5;
    const int lane = tid & 31;
    const int j    = blockIdx.x * 8 + warp;     // h index this warp owns

    const int r[4] = { j, j + HDIM, j + 2 * HDIM, j + 3 * HDIM };

    // ---- Recurrent weights, register-resident as f32x2 pairs.
    // Thread owns column pairs c = 2*lane + 64*k, k = 0..15  (32 h-columns). ----
    unsigned long long wh[4][16];
    #pragma unroll
    for (int g = 0; g < 4; g++)
        #pragma unroll
        for (int k = 0; k < 16; k++)
            wh[g][k] = ld64(W_hh + (size_t)r[g] * HDIM + 2 * lane + 64 * k);

    // ---- Input-projection weights: pairs c = 2*lane + 64*k, k = 0..3. ----
    unsigned long long wx[4][4];
    #pragma unroll
    for (int g = 0; g < 4; g++)
        #pragma unroll
        for (int k = 0; k < 4; k++)
            wx[g][k] = ld64(W_ih + (size_t)r[g] * IDIM + 2 * lane + 64 * k);

    const float bias0 = b_ih[r[0]] + b_hh[r[0]];
    const float bias1 = b_ih[r[1]] + b_hh[r[1]];
    const float bias2 = b_ih[r[2]] + b_hh[r[2]];
    const float bias3 = b_ih[r[3]] + b_hh[r[3]];

    // x_t pairs, prefetched one step ahead
    unsigned long long xr[4];
    #pragma unroll
    for (int k = 0; k < 4; k++)
        xr[k] = ld64(seq + 2 * lane + 64 * k);

    float c_state = 0.0f;   // meaningful on lane 0 only

    const unsigned int* hpoll =
        reinterpret_cast<const unsigned int*>(g_hs) + 4 * tid;

    #pragma unroll 1
    for (int t = 0; t < T_STEPS; ++t) {
        // ---- Poll h_{t} directly: all 1024 elements non-sentinel => ready.
        // The validated load IS the data; no flags, no fences, no atomics. ----
        const unsigned int* p = hpoll + (size_t)t * HDIM;
        unsigned int v0, v1, v2, v3;
        for (;;) {
            asm volatile("ld.global.cg.v4.b32 {%0,%1,%2,%3}, [%4];"
                         : "=r"(v0), "=r"(v1), "=r"(v2), "=r"(v3) : "l"(p));
            int ok = (v0 != NAN_BITS) & (v1 != NAN_BITS) &
                     (v2 != NAN_BITS) & (v3 != NAN_BITS);
            if (__syncthreads_and(ok)) break;
        }
        reinterpret_cast<uint4*>(h_s)[tid] = make_uint4(v0, v1, v2, v3);
        __syncthreads();

        // ---- Gates: acc starts from the x-projection, then h matvec. ----
        unsigned long long a0 = 0, a1 = 0, a2 = 0, a3 = 0;
        #pragma unroll
        for (int k = 0; k < 4; k++) {
            fma2(a0, wx[0][k], xr[k]);
            fma2(a1, wx[1][k], xr[k]);
            fma2(a2, wx[2][k], xr[k]);
            fma2(a3, wx[3][k], xr[k]);
        }
        #pragma unroll
        for (int k = 0; k < 16; k++) {
            unsigned long long hv = ld64(h_s + 2 * lane + 64 * k);
            fma2(a0, wh[0][k], hv);
            fma2(a1, wh[1][k], hv);
            fma2(a2, wh[2][k], hv);
            fma2(a3, wh[3][k], hv);
        }

        float s0 = pairsum(a0), s1 = pairsum(a1),
              s2 = pairsum(a2), s3 = pairsum(a3);
        #pragma unroll
        for (int off = 16; off > 0; off >>= 1) {
            s0 += __shfl_xor_sync(0xffffffffu, s0, off);
            s1 += __shfl_xor_sync(0xffffffffu, s1, off);
            s2 += __shfl_xor_sync(0xffffffffu, s2, off);
            s3 += __shfl_xor_sync(0xffffffffu, s3, off);
        }

        // ---- LSTM cell on lane 0; publish h_{t+1} (write-through to L2). ----
        if (lane == 0) {
            float i_ = sigmoid_fast(s0 + bias0);
            float f_ = sigmoid_fast(s1 + bias1);
            float g_ = tanh_fast   (s2 + bias2);
            float o_ = sigmoid_fast(s3 + bias3);
            c_state = f_ * c_state + i_ * g_;
            float h_ = o_ * tanh_fast(c_state);
            asm volatile("st.global.cg.f32 [%0], %1;"
                         :: "l"(g_hs + (size_t)(t + 1) * HDIM + j), "f"(h_));
        }

        // ---- Prefetch x_{t+1}; latency hides behind the next poll. ----
        if (t + 1 < T_STEPS) {
            const float* xrow = seq + (size_t)(t + 1) * IDIM;
            #pragma unroll
            for (int k = 0; k < 4; k++)
                xr[k] = ld64(xrow + 2 * lane + 64 * k);
        }
    }
}

// out[t] = sigmoid(h_{t+1} . W_out + b_out); one warp per timestep.
__global__ void __launch_bounds__(256)
out_kernel(const float* __restrict__ W_out,
           const float* __restrict__ b_out,
           float* __restrict__ out)
{
    const int warp = threadIdx.x >> 5;
    const int lane = threadIdx.x & 31;
    const int t = blockIdx.x * 8 + warp;
    if (t >= T_STEPS) return;

    const float* hrow = g_hs + (size_t)(t + 1) * HDIM;
    float acc = 0.0f;
    #pragma unroll
    for (int k = 0; k < 32; k++) {
        int c = lane + 32 * k;
        acc = fmaf(hrow[c], W_out[c], acc);
    }
    #pragma unroll
    for (int off = 16; off > 0; off >>= 1)
        acc += __shfl_xor_sync(0xffffffffu, acc, off);
    if (lane == 0)
        out[t] = sigmoid_fast(acc + b_out[0]);
}

extern "C" void kernel_launch(void* const* d_in, const int* in_sizes, int n_in,
                              void* d_out, int out_size)
{
    const float* seq   = (const float*)d_in[0];   // [8192, 256]
    const float* W_ih  = (const float*)d_in[1];   // [4096, 256]
    const float* W_hh  = (const float*)d_in[2];   // [4096, 1024]
    const float* b_ih  = (const float*)d_in[3];   // [4096]
    const float* b_hh  = (const float*)d_in[4];   // [4096]
    const float* W_out = (const float*)d_in[5];   // [1, 1024]
    const float* b_out = (const float*)d_in[6];   // [1]
    float* out = (float*)d_out;                   // [8192, 1]

    init_kernel<<<T_STEPS + 1, NTHREADS>>>();
    lstm_kernel<<<NBLOCKS, NTHREADS>>>(seq, W_ih, W_hh, b_ih, b_hh);
    out_kernel<<<T_STEPS / 8, 256>>>(W_out, b_out, out);
}

// round 4
// speedup vs baseline: 1.2715x; 1.2715x over previous
#include <cuda_runtime.h>

#define T_STEPS 8192
#define IDIM 256
#define HDIM 1024
#define NBLOCKS 128
#define NTHREADS 256       // 8 warps; warp w handles h index j = 8*block + w
#define NAN_BITS 0x7fc00000u

// h history: row t holds h_{t-1} (input to step t). Row 0 = zeros (h_0).
// Rows 1..T start as sentinel NaN; a non-sentinel value == "published".
// h = o*tanh(c) is bounded in (-1,1): no finite output collides with the sentinel.
__device__ __align__(16) float g_hs[(T_STEPS + 1) * HDIM];

// Fill row 0 with zeros, rows 1..T with sentinel. One block per row.
__global__ void init_kernel() {
    unsigned int v = (blockIdx.x == 0) ? 0u : NAN_BITS;
    uint4 q = make_uint4(v, v, v, v);
    reinterpret_cast<uint4*>(g_hs + (size_t)blockIdx.x * HDIM)[threadIdx.x] = q;
}

__device__ __forceinline__ float sigmoid_fast(float x) {
    return 1.0f / (1.0f + __expf(-x));
}
__device__ __forceinline__ float tanh_fast(float x) {
    return fmaf(2.0f, 1.0f / (1.0f + __expf(-2.0f * x)), -1.0f);
}

// Packed dual-FMA: d.xy += a.xy * b.xy  (Blackwell f32x2, PTX-only)
__device__ __forceinline__ void fma2(unsigned long long& d,
                                     unsigned long long a,
                                     unsigned long long b) {
    asm("fma.rn.f32x2 %0, %1, %2, %0;" : "+l"(d) : "l"(a), "l"(b));
}
__device__ __forceinline__ unsigned long long ld64(const float* p) {
    return *reinterpret_cast<const unsigned long long*>(p);
}
__device__ __forceinline__ float pairsum(unsigned long long v) {
    float2 f = *reinterpret_cast<float2*>(&v);
    return f.x + f.y;
}

__global__ void __launch_bounds__(NTHREADS, 1)
lstm_kernel(const float* __restrict__ seq,
            const float* __restrict__ W_ih,
            const float* __restrict__ W_hh,
            const float* __restrict__ b_ih,
            const float* __restrict__ b_hh)
{
    __shared__ __align__(16) float h_s[HDIM];   // single buffer, as in passing R2

    const int tid  = threadIdx.x;
    const int warp = tid >> 5;
    const int lane = tid & 31;
    const int j    = blockIdx.x * 8 + warp;     // h index this warp owns

    const int r[4] = { j, j + HDIM, j + 2 * HDIM, j + 3 * HDIM };

    // ---- Recurrent weights, register-resident as f32x2 pairs.
    // Thread owns column pairs c = 2*lane + 64*k, k = 0..15  (32 h-columns). ----
    unsigned long long wh[4][16];
    #pragma unroll
    for (int g = 0; g < 4; g++)
        #pragma unroll
        for (int k = 0; k < 16; k++)
            wh[g][k] = ld64(W_hh + (size_t)r[g] * HDIM + 2 * lane + 64 * k);

    // ---- Input-projection weights: pairs c = 2*lane + 64*k, k = 0..3. ----
    unsigned long long wx[4][4];
    #pragma unroll
    for (int g = 0; g < 4; g++)
        #pragma unroll
        for (int k = 0; k < 4; k++)
            wx[g][k] = ld64(W_ih + (size_t)r[g] * IDIM + 2 * lane + 64 * k);

    const float bias0 = b_ih[r[0]] + b_hh[r[0]];
    const float bias1 = b_ih[r[1]] + b_hh[r[1]];
    const float bias2 = b_ih[r[2]] + b_hh[r[2]];
    const float bias3 = b_ih[r[3]] + b_hh[r[3]];

    // x_t pairs, prefetched one step ahead
    unsigned long long xr[4];
    #pragma unroll
    for (int k = 0; k < 4; k++)
        xr[k] = ld64(seq + 2 * lane + 64 * k);

    float c_state = 0.0f;   // meaningful on lane 0 only

    const unsigned int* hpoll =
        reinterpret_cast<const unsigned int*>(g_hs) + 4 * tid;

    #pragma unroll 1
    for (int t = 0; t < T_STEPS; ++t) {
        // ---- Sentinel poll, STICKY per-thread chunk (sole change vs R2):
        // each thread loads only its own 16B chunk, and once that chunk is
        // ready it stops loading and just re-joins the and-barrier. Exit is
        // block-uniform exactly as in R2. ----
        const unsigned int* p = hpoll + (size_t)t * HDIM;
        unsigned int v0, v1, v2, v3;
        int ok = 0;
        for (;;) {
            if (!ok) {
                asm volatile("ld.global.cg.v4.b32 {%0,%1,%2,%3}, [%4];"
                             : "=r"(v0), "=r"(v1), "=r"(v2), "=r"(v3) : "l"(p));
                ok = (v0 != NAN_BITS) & (v1 != NAN_BITS) &
                     (v2 != NAN_BITS) & (v3 != NAN_BITS);
            }
            if (__syncthreads_and(ok)) break;
        }
        reinterpret_cast<uint4*>(h_s)[tid] = make_uint4(v0, v1, v2, v3);
        __syncthreads();

        // ---- Gates: acc starts from the x-projection, then h matvec. ----
        unsigned long long a0 = 0, a1 = 0, a2 = 0, a3 = 0;
        #pragma unroll
        for (int k = 0; k < 4; k++) {
            fma2(a0, wx[0][k], xr[k]);
            fma2(a1, wx[1][k], xr[k]);
            fma2(a2, wx[2][k], xr[k]);
            fma2(a3, wx[3][k], xr[k]);
        }
        #pragma unroll
        for (int k = 0; k < 16; k++) {
            unsigned long long hv = ld64(h_s + 2 * lane + 64 * k);
            fma2(a0, wh[0][k], hv);
            fma2(a1, wh[1][k], hv);
            fma2(a2, wh[2][k], hv);
            fma2(a3, wh[3][k], hv);
        }

        float s0 = pairsum(a0), s1 = pairsum(a1),
              s2 = pairsum(a2), s3 = pairsum(a3);
        #pragma unroll
        for (int off = 16; off > 0; off >>= 1) {
            s0 += __shfl_xor_sync(0xffffffffu, s0, off);
            s1 += __shfl_xor_sync(0xffffffffu, s1, off);
            s2 += __shfl_xor_sync(0xffffffffu, s2, off);
            s3 += __shfl_xor_sync(0xffffffffu, s3, off);
        }

        // ---- LSTM cell on lane 0; publish h_{t+1} (write-through to L2). ----
        if (lane == 0) {
            float i_ = sigmoid_fast(s0 + bias0);
            float f_ = sigmoid_fast(s1 + bias1);
            float g_ = tanh_fast   (s2 + bias2);
            float o_ = sigmoid_fast(s3 + bias3);
            c_state = f_ * c_state + i_ * g_;
            float h_ = o_ * tanh_fast(c_state);
            asm volatile("st.global.cg.f32 [%0], %1;"
                         :: "l"(g_hs + (size_t)(t + 1) * HDIM + j), "f"(h_));
        }

        // ---- Prefetch x_{t+1}; latency hides behind the next poll. ----
        if (t + 1 < T_STEPS) {
            const float* xrow = seq + (size_t)(t + 1) * IDIM;
            #pragma unroll
            for (int k = 0; k < 4; k++)
                xr[k] = ld64(xrow + 2 * lane + 64 * k);
        }
    }
}

// out[t] = sigmoid(h_{t+1} . W_out + b_out); one warp per timestep.
__global__ void __launch_bounds__(256)
out_kernel(const float* __restrict__ W_out,
           const float* __restrict__ b_out,
           float* __restrict__ out)
{
    const int warp = threadIdx.x >> 5;
    const int lane = threadIdx.x & 31;
    const int t = blockIdx.x * 8 + warp;
    if (t >= T_STEPS) return;

    const float* hrow = g_hs + (size_t)(t + 1) * HDIM;
    float acc = 0.0f;
    #pragma unroll
    for (int k = 0; k < 32; k++) {
        int c = lane + 32 * k;
        acc = fmaf(hrow[c], W_out[c], acc);
    }
    #pragma unroll
    for (int off = 16; off > 0; off >>= 1)
        acc += __shfl_xor_sync(0xffffffffu, acc, off);
    if (lane == 0)
        out[t] = sigmoid_fast(acc + b_out[0]);
}

extern "C" void kernel_launch(void* const* d_in, const int* in_sizes, int n_in,
                              void* d_out, int out_size)
{
    const float* seq   = (const float*)d_in[0];   // [8192, 256]
    const float* W_ih  = (const float*)d_in[1];   // [4096, 256]
    const float* W_hh  = (const float*)d_in[2];   // [4096, 1024]
    const float* b_ih  = (const float*)d_in[3];   // [4096]
    const float* b_hh  = (const float*)d_in[4];   // [4096]
    const float* W_out = (const float*)d_in[5];   // [1, 1024]
    const float* b_out = (const float*)d_in[6];   // [1]
    float* out = (float*)d_out;                   // [8192, 1]

    init_kernel<<<T_STEPS + 1, NTHREADS>>>();
    lstm_kernel<<<NBLOCKS, NTHREADS>>>(seq, W_ih, W_hh, b_ih, b_hh);
    out_kernel<<<T_STEPS / 8, 256>>>(W_out, b_out, out);
}

// round 5
// speedup vs baseline: 2.4391x; 1.9182x over previous
#include <cuda_runtime.h>

#define T_STEPS 8192
#define IDIM 256
#define HDIM 1024
#define NBLOCKS 128
#define NTHREADS 256       // 8 warps; warp w handles h index j = 8*block + w

// h history: row t holds h_{t-1} (input to step t). Row 0 = zeros (h_0).
__device__ __align__(16) float g_hs[(T_STEPS + 1) * HDIM];
// Arrival counter: one release-increment per block per step.
__device__ unsigned int g_count;

__global__ void init_kernel() {
    reinterpret_cast<float4*>(g_hs)[threadIdx.x] = make_float4(0.f, 0.f, 0.f, 0.f);
    if (threadIdx.x == 0) g_count = 0u;
}

__device__ __forceinline__ float sigmoid_fast(float x) {
    return 1.0f / (1.0f + __expf(-x));
}
__device__ __forceinline__ float tanh_fast(float x) {
    return fmaf(2.0f, 1.0f / (1.0f + __expf(-2.0f * x)), -1.0f);
}

// Packed dual-FMA: d.xy += a.xy * b.xy  (Blackwell f32x2, PTX-only)
__device__ __forceinline__ void fma2(unsigned long long& d,
                                     unsigned long long a,
                                     unsigned long long b) {
    asm("fma.rn.f32x2 %0, %1, %2, %0;" : "+l"(d) : "l"(a), "l"(b));
}
__device__ __forceinline__ unsigned long long ld64(const float* p) {
    return *reinterpret_cast<const unsigned long long*>(p);
}
__device__ __forceinline__ float pairsum(unsigned long long v) {
    float2 f = *reinterpret_cast<float2*>(&v);
    return f.x + f.y;
}

__global__ void __launch_bounds__(NTHREADS, 1)
lstm_kernel(const float* __restrict__ seq,
            const float* __restrict__ W_ih,
            const float* __restrict__ W_hh,
            const float* __restrict__ b_ih,
            const float* __restrict__ b_hh)
{
    __shared__ __align__(16) float h_s[HDIM];

    const int tid  = threadIdx.x;
    const int warp = tid >> 5;
    const int lane = tid & 31;
    const int j    = blockIdx.x * 8 + warp;     // h index this warp owns

    const int r[4] = { j, j + HDIM, j + 2 * HDIM, j + 3 * HDIM };

    // ---- Recurrent weights, register-resident as f32x2 pairs.
    // Thread owns column pairs c = 2*lane + 64*k, k = 0..15  (32 h-columns). ----
    unsigned long long wh[4][16];
    #pragma unroll
    for (int g = 0; g < 4; g++)
        #pragma unroll
        for (int k = 0; k < 16; k++)
            wh[g][k] = ld64(W_hh + (size_t)r[g] * HDIM + 2 * lane + 64 * k);

    // ---- Input-projection weights: pairs c = 2*lane + 64*k, k = 0..3. ----
    unsigned long long wx[4][4];
    #pragma unroll
    for (int g = 0; g < 4; g++)
        #pragma unroll
        for (int k = 0; k < 4; k++)
            wx[g][k] = ld64(W_ih + (size_t)r[g] * IDIM + 2 * lane + 64 * k);

    const float bias0 = b_ih[r[0]] + b_hh[r[0]];
    const float bias1 = b_ih[r[1]] + b_hh[r[1]];
    const float bias2 = b_ih[r[2]] + b_hh[r[2]];
    const float bias3 = b_ih[r[3]] + b_hh[r[3]];

    // x_t pairs, prefetched one step ahead
    unsigned long long xr[4];
    #pragma unroll
    for (int k = 0; k < 4; k++)
        xr[k] = ld64(seq + 2 * lane + 64 * k);

    float c_state = 0.0f;   // meaningful on lane 0 only

    #pragma unroll 1
    for (int t = 0; t < T_STEPS; ++t) {
        // ---- x-projection first: depends only on prefetched xr, runs in the
        // shadow of the poll barrier below. ----
        unsigned long long a0 = 0, a1 = 0, a2 = 0, a3 = 0;
        #pragma unroll
        for (int k = 0; k < 4; k++) {
            fma2(a0, wx[0][k], xr[k]);
            fma2(a1, wx[1][k], xr[k]);
            fma2(a2, wx[2][k], xr[k]);
            fma2(a3, wx[3][k], xr[k]);
        }

        // ---- Wait until all 128 blocks have published h_t (counter >= 128*t).
        // Single thread polls a single address with acquire loads. ----
        if (tid == 0) {
            const unsigned int target = (unsigned int)NBLOCKS * (unsigned int)t;
            unsigned int v;
            do {
                asm volatile("ld.acquire.gpu.global.u32 %0, [%1];"
                             : "=r"(v) : "l"(&g_count));
            } while (v < target);
        }
        __syncthreads();

        // ---- Stage h_t into SMEM (L2-coherent load). ----
        {
            float4 hv = __ldcg(reinterpret_cast<const float4*>(
                                   g_hs + (size_t)t * HDIM) + tid);
            reinterpret_cast<float4*>(h_s)[tid] = hv;
        }
        __syncthreads();

        // ---- Recurrent matvec: register weights vs SMEM h, packed f32x2. ----
        #pragma unroll
        for (int k = 0; k < 16; k++) {
            unsigned long long hv = ld64(h_s + 2 * lane + 64 * k);
            fma2(a0, wh[0][k], hv);
            fma2(a1, wh[1][k], hv);
            fma2(a2, wh[2][k], hv);
            fma2(a3, wh[3][k], hv);
        }

        float s0 = pairsum(a0), s1 = pairsum(a1),
              s2 = pairsum(a2), s3 = pairsum(a3);
        #pragma unroll
        for (int off = 16; off > 0; off >>= 1) {
            s0 += __shfl_xor_sync(0xffffffffu, s0, off);
            s1 += __shfl_xor_sync(0xffffffffu, s1, off);
            s2 += __shfl_xor_sync(0xffffffffu, s2, off);
            s3 += __shfl_xor_sync(0xffffffffu, s3, off);
        }

        // ---- LSTM cell on lane 0; publish h_{t+1} (write-through to L2). ----
        if (lane == 0) {
            float i_ = sigmoid_fast(s0 + bias0);
            float f_ = sigmoid_fast(s1 + bias1);
            float g_ = tanh_fast   (s2 + bias2);
            float o_ = sigmoid_fast(s3 + bias3);
            c_state = f_ * c_state + i_ * g_;
            float h_ = o_ * tanh_fast(c_state);
            asm volatile("st.global.cg.f32 [%0], %1;"
                         :: "l"(g_hs + (size_t)(t + 1) * HDIM + j), "f"(h_));
        }
        __syncthreads();    // all warps' h stores sequenced before the arrive;
                            // also protects h_s reuse next iteration.

        // ---- Single release-increment per block: barrier gives intra-block
        // happens-before, release op is cumulative => consumers that observe
        // the count see all 8 h stores. Replaces 8x threadfence + atomicAdd. ----
        if (tid == 0) {
            asm volatile("red.release.gpu.global.add.u32 [%0], %1;"
                         :: "l"(&g_count), "r"(1u));
        }

        // ---- Prefetch x_{t+1}; latency hides behind the next poll. ----
        if (t + 1 < T_STEPS) {
            const float* xrow = seq + (size_t)(t + 1) * IDIM + 2 * lane;
            #pragma unroll
            for (int k = 0; k < 4; k++)
                xr[k] = ld64(xrow + 64 * k);
        }
    }
}

// out[t] = sigmoid(h_{t+1} . W_out + b_out); one warp per timestep.
__global__ void __launch_bounds__(256)
out_kernel(const float* __restrict__ W_out,
           const float* __restrict__ b_out,
           float* __restrict__ out)
{
    const int warp = threadIdx.x >> 5;
    const int lane = threadIdx.x & 31;
    const int t = blockIdx.x * 8 + warp;
    if (t >= T_STEPS) return;

    const float* hrow = g_hs + (size_t)(t + 1) * HDIM;
    float acc = 0.0f;
    #pragma unroll
    for (int k = 0; k < 32; k++) {
        int c = lane + 32 * k;
        acc = fmaf(hrow[c], W_out[c], acc);
    }
    #pragma unroll
    for (int off = 16; off > 0; off >>= 1)
        acc += __shfl_xor_sync(0xffffffffu, acc, off);
    if (lane == 0)
        out[t] = sigmoid_fast(acc + b_out[0]);
}

extern "C" void kernel_launch(void* const* d_in, const int* in_sizes, int n_in,
                              void* d_out, int out_size)
{
    const float* seq   = (const float*)d_in[0];   // [8192, 256]
    const float* W_ih  = (const float*)d_in[1];   // [4096, 256]
    const float* W_hh  = (const float*)d_in[2];   // [4096, 1024]
    const float* b_ih  = (const float*)d_in[3];   // [4096]
    const float* b_hh  = (const float*)d_in[4];   // [4096]
    const float* W_out = (const float*)d_in[5];   // [1, 1024]
    const float* b_out = (const float*)d_in[6];   // [1]
    float* out = (float*)d_out;                   // [8192, 1]

    init_kernel<<<1, 256>>>();
    lstm_kernel<<<NBLOCKS, NTHREADS>>>(seq, W_ih, W_hh, b_ih, b_hh);
    out_kernel<<<T_STEPS / 8, 256>>>(W_out, b_out, out);
}

// round 6
// speedup vs baseline: 3.9769x; 1.6305x over previous
#include <cuda_runtime.h>

#define T_STEPS 8192
#define IDIM 256
#define HDIM 1024
#define NBLOCKS 128
#define NTHREADS 256       // 8 warps; warp w handles h index j = 8*block + w
#define NAN_BITS 0x7fc00000u

// h history: row t holds h_{t-1} (input to step t). Row 0 = zeros (h_0).
// Rows 1..T start as sentinel NaN. Each element is written EXACTLY ONCE
// (by one producer warp's lane 0), so any non-sentinel read is the final
// value — the validated load IS the synchronization. h = o*tanh(c) ∈ (-1,1)
// can never equal the sentinel bit pattern.
__device__ __align__(16) float g_hs[(T_STEPS + 1) * HDIM];

// Fill row 0 with zeros, rows 1..T with sentinel. One block per row.
// Runs inside the graph, so every replay re-arms the sentinels.
__global__ void init_kernel() {
    unsigned int v = (blockIdx.x == 0) ? 0u : NAN_BITS;
    uint4 q = make_uint4(v, v, v, v);
    reinterpret_cast<uint4*>(g_hs + (size_t)blockIdx.x * HDIM)[threadIdx.x] = q;
}

__device__ __forceinline__ float sigmoid_fast(float x) {
    return 1.0f / (1.0f + __expf(-x));
}
__device__ __forceinline__ float tanh_fast(float x) {
    return fmaf(2.0f, 1.0f / (1.0f + __expf(-2.0f * x)), -1.0f);
}

// Packed dual-FMA: d.xy += a.xy * b.xy  (Blackwell f32x2, PTX-only)
__device__ __forceinline__ void fma2(unsigned long long& d,
                                     unsigned long long a,
                                     unsigned long long b) {
    asm("fma.rn.f32x2 %0, %1, %2, %0;" : "+l"(d) : "l"(a), "l"(b));
}
__device__ __forceinline__ unsigned long long ld64(const float* p) {
    return *reinterpret_cast<const unsigned long long*>(p);
}
__device__ __forceinline__ float pairsum(unsigned long long v) {
    float2 f = *reinterpret_cast<float2*>(&v);
    return f.x + f.y;
}

__global__ void __launch_bounds__(NTHREADS, 1)
lstm_kernel(const float* __restrict__ seq,
            const float* __restrict__ W_ih,
            const float* __restrict__ W_hh,
            const float* __restrict__ b_ih,
            const float* __restrict__ b_hh)
{
    __shared__ __align__(16) float h_s[HDIM];

    const int tid  = threadIdx.x;
    const int warp = tid >> 5;
    const int lane = tid & 31;
    const int j    = blockIdx.x * 8 + warp;     // h index this warp owns

    const int r[4] = { j, j + HDIM, j + 2 * HDIM, j + 3 * HDIM };

    // ---- Recurrent weights, register-resident as f32x2 pairs.
    // Thread owns column pairs c = 2*lane + 64*k, k = 0..15  (32 h-columns). ----
    unsigned long long wh[4][16];
    #pragma unroll
    for (int g = 0; g < 4; g++)
        #pragma unroll
        for (int k = 0; k < 16; k++)
            wh[g][k] = ld64(W_hh + (size_t)r[g] * HDIM + 2 * lane + 64 * k);

    // ---- Input-projection weights: pairs c = 2*lane + 64*k, k = 0..3. ----
    unsigned long long wx[4][4];
    #pragma unroll
    for (int g = 0; g < 4; g++)
        #pragma unroll
        for (int k = 0; k < 4; k++)
            wx[g][k] = ld64(W_ih + (size_t)r[g] * IDIM + 2 * lane + 64 * k);

    const float bias0 = b_ih[r[0]] + b_hh[r[0]];
    const float bias1 = b_ih[r[1]] + b_hh[r[1]];
    const float bias2 = b_ih[r[2]] + b_hh[r[2]];
    const float bias3 = b_ih[r[3]] + b_hh[r[3]];

    // x_t pairs, prefetched one step ahead
    unsigned long long xr[4];
    #pragma unroll
    for (int k = 0; k < 4; k++)
        xr[k] = ld64(seq + 2 * lane + 64 * k);

    float c_state = 0.0f;   // meaningful on lane 0 only

    #pragma unroll 1
    for (int t = 0; t < T_STEPS; ++t) {
        // ---- x-projection first: independent of h_t, overlaps the poll. ----
        unsigned long long a0 = 0, a1 = 0, a2 = 0, a3 = 0;
        #pragma unroll
        for (int k = 0; k < 4; k++) {
            fma2(a0, wx[0][k], xr[k]);
            fma2(a1, wx[1][k], xr[k]);
            fma2(a2, wx[2][k], xr[k]);
            fma2(a3, wx[3][k], xr[k]);
        }

        // ---- Warp-granular sentinel poll: warp w owns segment
        // h_t[128w .. 128w+127]; each lane polls its own 16B chunk (sticky),
        // warp exits via vote the moment its segment is complete. No block
        // barrier in the loop, no flags, no atomics, no fences. ----
        const float* p = g_hs + (size_t)t * HDIM + 128 * warp + 4 * lane;
        unsigned int v0, v1, v2, v3;
        int ok = 0;
        do {
            if (!ok) {
                asm volatile("ld.global.cg.v4.b32 {%0,%1,%2,%3}, [%4];"
                             : "=r"(v0), "=r"(v1), "=r"(v2), "=r"(v3) : "l"(p));
                ok = (v0 != NAN_BITS) & (v1 != NAN_BITS) &
                     (v2 != NAN_BITS) & (v3 != NAN_BITS);
            }
        } while (!__all_sync(0xffffffffu, ok));

        // Stage this warp's segment; one block barrier per step.
        reinterpret_cast<uint4*>(h_s)[tid] = make_uint4(v0, v1, v2, v3);
        __syncthreads();

        // ---- Recurrent matvec: register weights vs SMEM h, packed f32x2. ----
        #pragma unroll
        for (int k = 0; k < 16; k++) {
            unsigned long long hv = ld64(h_s + 2 * lane + 64 * k);
            fma2(a0, wh[0][k], hv);
            fma2(a1, wh[1][k], hv);
            fma2(a2, wh[2][k], hv);
            fma2(a3, wh[3][k], hv);
        }

        float s0 = pairsum(a0), s1 = pairsum(a1),
              s2 = pairsum(a2), s3 = pairsum(a3);
        #pragma unroll
        for (int off = 16; off > 0; off >>= 1) {
            s0 += __shfl_xor_sync(0xffffffffu, s0, off);
            s1 += __shfl_xor_sync(0xffffffffu, s1, off);
            s2 += __shfl_xor_sync(0xffffffffu, s2, off);
            s3 += __shfl_xor_sync(0xffffffffu, s3, off);
        }

        // ---- LSTM cell on lane 0; publish h_{t+1} straight to L2.
        // The store itself is the completion signal (single-write row). ----
        if (lane == 0) {
            float i_ = sigmoid_fast(s0 + bias0);
            float f_ = sigmoid_fast(s1 + bias1);
            float g_ = tanh_fast   (s2 + bias2);
            float o_ = sigmoid_fast(s3 + bias3);
            c_state = f_ * c_state + i_ * g_;
            float h_ = o_ * tanh_fast(c_state);
            asm volatile("st.global.cg.f32 [%0], %1;"
                         :: "l"(g_hs + (size_t)(t + 1) * HDIM + j), "f"(h_));
        }
        // NOTE: no trailing barrier needed — the next iteration's poll-exit
        // vote plus the single __syncthreads protect h_s reuse (h_s is only
        // rewritten after every warp passed this step's barrier and its own
        // next-step vote; readers of step t's h_s finished before the barrier
        // ... the barrier after staging orders write(t+1) after all reads(t)?
        // Write(t+1) happens after the warp's poll at t+1, which it can reach
        // before other warps finish reading h_s at step t. Guard it:
        __syncthreads();

        // ---- Prefetch x_{t+1}; latency hides behind the next poll. ----
        if (t + 1 < T_STEPS) {
            const float* xrow = seq + (size_t)(t + 1) * IDIM + 2 * lane;
            #pragma unroll
            for (int k = 0; k < 4; k++)
                xr[k] = ld64(xrow + 64 * k);
        }
    }
}

// out[t] = sigmoid(h_{t+1} . W_out + b_out); one warp per timestep.
__global__ void __launch_bounds__(256)
out_kernel(const float* __restrict__ W_out,
           const float* __restrict__ b_out,
           float* __restrict__ out)
{
    const int warp = threadIdx.x >> 5;
    const int lane = threadIdx.x & 31;
    const int t = blockIdx.x * 8 + warp;
    if (t >= T_STEPS) return;

    const float* hrow = g_hs + (size_t)(t + 1) * HDIM;
    float acc = 0.0f;
    #pragma unroll
    for (int k = 0; k < 32; k++) {
        int c = lane + 32 * k;
        acc = fmaf(hrow[c], W_out[c], acc);
    }
    #pragma unroll
    for (int off = 16; off > 0; off >>= 1)
        acc += __shfl_xor_sync(0xffffffffu, acc, off);
    if (lane == 0)
        out[t] = sigmoid_fast(acc + b_out[0]);
}

extern "C" void kernel_launch(void* const* d_in, const int* in_sizes, int n_in,
                              void* d_out, int out_size)
{
    const float* seq   = (const float*)d_in[0];   // [8192, 256]
    const float* W_ih  = (const float*)d_in[1];   // [4096, 256]
    const float* W_hh  = (const float*)d_in[2];   // [4096, 1024]
    const float* b_ih  = (const float*)d_in[3];   // [4096]
    const float* b_hh  = (const float*)d_in[4];   // [4096]
    const float* W_out = (const float*)d_in[5];   // [1, 1024]
    const float* b_out = (const float*)d_in[6];   // [1]
    float* out = (float*)d_out;                   // [8192, 1]

    init_kernel<<<T_STEPS + 1, NTHREADS>>>();
    lstm_kernel<<<NBLOCKS, NTHREADS>>>(seq, W_ih, W_hh, b_ih, b_hh);
    out_kernel<<<T_STEPS / 8, 256>>>(W_out, b_out, out);
}